// round 15
// baseline (speedup 1.0000x reference)
#include <cuda_runtime.h>
#include <cuda_fp16.h>
#include <cmath>
#include <cstdint>

#define NN     100000
#define EE     3200000
#define ETOT   (EE + NN)
#define FIN    512
#define H1D    64
#define HEADS  8
#define NCLS   16
#define SCAN_BS 512

// ---------------- scratch (device globals; no allocation) ----------------
__device__ __align__(16) static int    g_csr_src[ETOT];
__device__ static int    g_rowptr[NN + 1];
__device__ static int    g_cursor[NN];
__device__ static int    g_blocksum[512];
__device__ __align__(16) static __half g_h1h[(size_t)NN * H1D];  // fp16 h1
__device__ __align__(16) static float  g_as1[NN * HEADS];
__device__ __align__(16) static float  g_ad1[NN * HEADS];
__device__ __align__(16) static float  g_acc1[(size_t)NN * H1D];
__device__ __align__(16) static float  g_h2[(size_t)NN * NCLS];
__device__ __align__(16) static float  g_as2[NN];
__device__ __align__(16) static float  g_ad2[NN];
__device__ static int g_is64;

__device__ __forceinline__ float lrelu(float v) { return v > 0.0f ? v : 0.2f * v; }
__device__ __forceinline__ uint32_t f2tf32(float f) {
    uint32_t r;
    asm("cvt.rna.tf32.f32 %0, %1;" : "=r"(r) : "f"(f));
    return r;
}

// ---------------- init: zero rowptr + detect edge dtype (block 0) ---------
__global__ void k_init(const int* __restrict__ ei, int n1) {
    int t = blockIdx.x * blockDim.x + threadIdx.x;
    if (t < n1) g_rowptr[t] = 0;
    if (blockIdx.x == 0) {
        __shared__ int s;
        if (threadIdx.x == 0) s = 1;
        __syncthreads();
        int bad = 0;
        for (int i = threadIdx.x; i < 1024; i += blockDim.x)
            if (ei[2 * i + 1] != 0) bad = 1;
        if (bad) atomicExch(&s, 0);
        __syncthreads();
        if (threadIdx.x == 0) g_is64 = s;
    }
}

// ---------------- histogram of dst (reads edge_index directly) -------------
__global__ void k_hist(const int* __restrict__ ei, int E, int N) {
    int t = blockIdx.x * blockDim.x + threadIdx.x;
    if (t >= E + N) return;
    int d;
    if (t < E) {
        d = g_is64 ? (int)((const long long*)ei)[(size_t)E + t]
                   : ei[(size_t)E + t];
    } else {
        d = t - E;
    }
    atomicAdd(&g_rowptr[d + 1], 1);
}

// ---------------- scan (rowptr): 2 kernels -----------------------------------
__global__ void k_scan1(int n) {
    __shared__ int sh[SCAN_BS];
    int i = blockIdx.x * SCAN_BS + threadIdx.x;
    int v = (i < n) ? g_rowptr[i] : 0;
    sh[threadIdx.x] = v;
    __syncthreads();
    for (int off = 1; off < SCAN_BS; off <<= 1) {
        int t = (threadIdx.x >= off) ? sh[threadIdx.x - off] : 0;
        __syncthreads();
        sh[threadIdx.x] += t;
        __syncthreads();
    }
    if (i < n) g_rowptr[i] = sh[threadIdx.x];
    if (threadIdx.x == SCAN_BS - 1) g_blocksum[blockIdx.x] = sh[threadIdx.x];
}
// each block computes its own exclusive offset over block sums (<=512 entries)
__global__ void k_scan3(int n) {
    __shared__ int off_s;
    int b = blockIdx.x;
    if (threadIdx.x < 32) {
        int sum = 0;
        for (int j = threadIdx.x; j < b; j += 32) sum += g_blocksum[j];
#pragma unroll
        for (int o = 16; o; o >>= 1) sum += __shfl_xor_sync(0xFFFFFFFFu, sum, o);
        if (threadIdx.x == 0) off_s = sum;
    }
    __syncthreads();
    int i = b * SCAN_BS + threadIdx.x;
    if (i < n) {
        int v = g_rowptr[i] + off_s;
        g_rowptr[i] = v;
        if (i < n - 1) g_cursor[i] = v;
    }
}

// ---------------- scatter (re-reads edge_index, decodes src+dst) -----------
__global__ void k_scatter(const int* __restrict__ ei, int E, int N) {
    int t = blockIdx.x * blockDim.x + threadIdx.x;
    if (t >= E + N) return;
    int s, d;
    if (t < E) {
        if (g_is64) {
            const long long* e64 = (const long long*)ei;
            s = (int)e64[t];
            d = (int)e64[(size_t)E + t];
        } else {
            s = ei[t];
            d = ei[(size_t)E + t];
        }
    } else {
        s = t - E;
        d = t - E;
    }
    int pos = atomicAdd(&g_cursor[d], 1);
    g_csr_src[pos] = s;
}

// ------- GEMM1 via tf32 mma.sync, fp16 h1 + fused attention epilogue -------
#define TBM 128
#define TBN 64
#define TBK 16
__global__ __launch_bounds__(256) void k_gemm1(const float* __restrict__ X,
                                               const float* __restrict__ W,
                                               const float* __restrict__ att_s,
                                               const float* __restrict__ att_d, int M) {
    __shared__ float xs[TBK][TBM + 4];
    __shared__ float ws[TBK][TBN + 4];
    const int tid = threadIdx.x;
    const int wid = tid >> 5, lane = tid & 31;
    const int wm = wid >> 1, wn = wid & 1;
    const int grp = lane >> 2, tcol = lane & 3;
    const int row0 = blockIdx.x * TBM;

    float c[2][4][4];
#pragma unroll
    for (int mt = 0; mt < 2; mt++)
#pragma unroll
        for (int nt = 0; nt < 4; nt++)
#pragma unroll
            for (int q = 0; q < 4; q++) c[mt][nt][q] = 0.0f;

    for (int k0 = 0; k0 < FIN; k0 += TBK) {
#pragma unroll
        for (int i = 0; i < 2; i++) {
            int s = tid + i * 256;
            int r = s >> 2;
            int c4 = s & 3;
            float4 v = make_float4(0.f, 0.f, 0.f, 0.f);
            int gr = row0 + r;
            if (gr < M)
                v = *(const float4*)(X + (size_t)gr * FIN + k0 + c4 * 4);
            xs[c4 * 4 + 0][r] = __uint_as_float(f2tf32(v.x));
            xs[c4 * 4 + 1][r] = __uint_as_float(f2tf32(v.y));
            xs[c4 * 4 + 2][r] = __uint_as_float(f2tf32(v.z));
            xs[c4 * 4 + 3][r] = __uint_as_float(f2tf32(v.w));
        }
        {
            int r = tid >> 4;
            int c4 = tid & 15;
            float4 v = *(const float4*)(W + (size_t)(k0 + r) * TBN + c4 * 4);
            ws[r][c4 * 4 + 0] = __uint_as_float(f2tf32(v.x));
            ws[r][c4 * 4 + 1] = __uint_as_float(f2tf32(v.y));
            ws[r][c4 * 4 + 2] = __uint_as_float(f2tf32(v.z));
            ws[r][c4 * 4 + 3] = __uint_as_float(f2tf32(v.w));
        }
        __syncthreads();
#pragma unroll
        for (int kc = 0; kc < 2; kc++) {
            const int kb = kc * 8;
            uint32_t a[2][4];
#pragma unroll
            for (int mt = 0; mt < 2; mt++) {
                int m0 = wm * 32 + mt * 16;
                a[mt][0] = __float_as_uint(xs[kb + tcol][m0 + grp]);
                a[mt][1] = __float_as_uint(xs[kb + tcol][m0 + grp + 8]);
                a[mt][2] = __float_as_uint(xs[kb + tcol + 4][m0 + grp]);
                a[mt][3] = __float_as_uint(xs[kb + tcol + 4][m0 + grp + 8]);
            }
            uint32_t b[4][2];
#pragma unroll
            for (int nt = 0; nt < 4; nt++) {
                int n0 = wn * 32 + nt * 8;
                b[nt][0] = __float_as_uint(ws[kb + tcol][n0 + grp]);
                b[nt][1] = __float_as_uint(ws[kb + tcol + 4][n0 + grp]);
            }
#pragma unroll
            for (int mt = 0; mt < 2; mt++)
#pragma unroll
                for (int nt = 0; nt < 4; nt++) {
                    asm volatile(
                        "mma.sync.aligned.m16n8k8.row.col.f32.tf32.tf32.f32 "
                        "{%0,%1,%2,%3}, {%4,%5,%6,%7}, {%8,%9}, {%0,%1,%2,%3};"
                        : "+f"(c[mt][nt][0]), "+f"(c[mt][nt][1]),
                          "+f"(c[mt][nt][2]), "+f"(c[mt][nt][3])
                        : "r"(a[mt][0]), "r"(a[mt][1]), "r"(a[mt][2]), "r"(a[mt][3]),
                          "r"(b[nt][0]), "r"(b[nt][1]));
                }
        }
        __syncthreads();
    }
    // epilogue: fp16 h1 store + fused attention projections.
    // nt tile = one head: head = wn*4 + nt; lane's channel pair = tcol*2.
#pragma unroll
    for (int mt = 0; mt < 2; mt++) {
#pragma unroll
        for (int nt = 0; nt < 4; nt++) {
            int head = wn * 4 + nt;
            int row = row0 + wm * 32 + mt * 16 + grp;
            int col = wn * 32 + nt * 8 + tcol * 2;
            if (row < M)
                *(__half2*)&g_h1h[(size_t)row * H1D + col] =
                    __floats2half2_rn(c[mt][nt][0], c[mt][nt][1]);
            if (row + 8 < M)
                *(__half2*)&g_h1h[(size_t)(row + 8) * H1D + col] =
                    __floats2half2_rn(c[mt][nt][2], c[mt][nt][3]);
            // attention partials: channels (tcol*2, tcol*2+1) of this head
            float s0 = __ldg(att_s + head * 8 + tcol * 2);
            float s1 = __ldg(att_s + head * 8 + tcol * 2 + 1);
            float d0 = __ldg(att_d + head * 8 + tcol * 2);
            float d1 = __ldg(att_d + head * 8 + tcol * 2 + 1);
            float asA = c[mt][nt][0] * s0 + c[mt][nt][1] * s1;  // row
            float adA = c[mt][nt][0] * d0 + c[mt][nt][1] * d1;
            float asB = c[mt][nt][2] * s0 + c[mt][nt][3] * s1;  // row+8
            float adB = c[mt][nt][2] * d0 + c[mt][nt][3] * d1;
            // reduce over tcol (lane bits 0-1)
            asA += __shfl_xor_sync(0xFFFFFFFFu, asA, 1);
            asA += __shfl_xor_sync(0xFFFFFFFFu, asA, 2);
            adA += __shfl_xor_sync(0xFFFFFFFFu, adA, 1);
            adA += __shfl_xor_sync(0xFFFFFFFFu, adA, 2);
            asB += __shfl_xor_sync(0xFFFFFFFFu, asB, 1);
            asB += __shfl_xor_sync(0xFFFFFFFFu, asB, 2);
            adB += __shfl_xor_sync(0xFFFFFFFFu, adB, 1);
            adB += __shfl_xor_sync(0xFFFFFFFFu, adB, 2);
            if (tcol == 0) {
                if (row < M) {
                    g_as1[row * 8 + head] = asA;
                    g_ad1[row * 8 + head] = adA;
                }
                if (row + 8 < M) {
                    g_as1[(row + 8) * 8 + head] = asB;
                    g_ad1[(row + 8) * 8 + head] = adB;
                }
            }
        }
    }
}

// ---------------- fused layer1, single pass, fp16 gathers -----------------
__global__ __launch_bounds__(256) void k_layer1(int N) {
    int w = (blockIdx.x * blockDim.x + threadIdx.x) >> 5;
    int lane = threadIdx.x & 31;
    if (w >= N) return;
    int beg = g_rowptr[w], end = g_rowptr[w + 1];
    int head = lane & 7;
    int eslot = lane >> 3;
    float adsel = g_ad1[w * 8 + head];

    float den = 0.0f;
    float acc[8];
#pragma unroll
    for (int j = 0; j < 8; j++) acc[j] = 0.0f;
    for (int e = beg + eslot; e < end; e += 4) {
        int s = g_csr_src[e];
        float p = __expf(lrelu(g_as1[s * 8 + head] + adsel));
        den += p;
        uint4 raw = *(const uint4*)&g_h1h[(size_t)s * H1D + head * 8];
        float2 q0 = __half22float2(*(__half2*)&raw.x);
        float2 q1 = __half22float2(*(__half2*)&raw.y);
        float2 q2 = __half22float2(*(__half2*)&raw.z);
        float2 q3 = __half22float2(*(__half2*)&raw.w);
        acc[0] += p * q0.x; acc[1] += p * q0.y;
        acc[2] += p * q1.x; acc[3] += p * q1.y;
        acc[4] += p * q2.x; acc[5] += p * q2.y;
        acc[6] += p * q3.x; acc[7] += p * q3.y;
    }
    den += __shfl_xor_sync(0xFFFFFFFFu, den, 8);
    den += __shfl_xor_sync(0xFFFFFFFFu, den, 16);
#pragma unroll
    for (int j = 0; j < 8; j++) {
        acc[j] += __shfl_xor_sync(0xFFFFFFFFu, acc[j], 8);
        acc[j] += __shfl_xor_sync(0xFFFFFFFFu, acc[j], 16);
    }
    if (eslot == 0) {
        float rden = 1.0f / den;
        *(float4*)&g_acc1[(size_t)w * H1D + head * 8] =
            make_float4(acc[0] * rden, acc[1] * rden, acc[2] * rden, acc[3] * rden);
        *(float4*)&g_acc1[(size_t)w * H1D + head * 8 + 4] =
            make_float4(acc[4] * rden, acc[5] * rden, acc[6] * rden, acc[7] * rden);
    }
}

// ---------------- finalize1: +b1, elu, @W2, attention dots ----------------
__global__ __launch_bounds__(256) void k_fin1(const float* __restrict__ b1,
                                              const float* __restrict__ W2,
                                              const float* __restrict__ as2v,
                                              const float* __restrict__ ad2v, int N) {
    __shared__ float w2s[H1D * NCLS];
    __shared__ float b1s[H1D];
    __shared__ float s2[NCLS], d2[NCLS];
    int tid = threadIdx.x;
    for (int i = tid; i < H1D * NCLS; i += blockDim.x) w2s[i] = W2[i];
    if (tid < H1D) b1s[tid] = b1[tid];
    if (tid < NCLS) { s2[tid] = as2v[tid]; d2[tid] = ad2v[tid]; }
    __syncthreads();
    int n = blockIdx.x * blockDim.x + tid;
    if (n >= N) return;

    float h[H1D];
    const float4* ap = (const float4*)g_acc1 + (size_t)n * 16;
#pragma unroll
    for (int q = 0; q < 16; q++) {
        float4 v = ap[q];
        h[q * 4 + 0] = v.x; h[q * 4 + 1] = v.y; h[q * 4 + 2] = v.z; h[q * 4 + 3] = v.w;
    }
#pragma unroll
    for (int c = 0; c < H1D; c++) {
        float v = h[c] + b1s[c];
        h[c] = v > 0.0f ? v : expm1f(v);
    }
    float o[NCLS];
#pragma unroll
    for (int j = 0; j < NCLS; j++) o[j] = 0.0f;
#pragma unroll
    for (int c = 0; c < H1D; c++) {
        float hv = h[c];
#pragma unroll
        for (int j = 0; j < NCLS; j++) o[j] += hv * w2s[c * NCLS + j];
    }
    float4* h2p = (float4*)g_h2 + (size_t)n * 4;
#pragma unroll
    for (int q = 0; q < 4; q++)
        h2p[q] = make_float4(o[q * 4], o[q * 4 + 1], o[q * 4 + 2], o[q * 4 + 3]);
    float as = 0.0f, ad = 0.0f;
#pragma unroll
    for (int j = 0; j < NCLS; j++) { as += o[j] * s2[j]; ad += o[j] * d2[j]; }
    g_as2[n] = as;
    g_ad2[n] = ad;
}

// ---------------- fused layer2, single pass -------------------------------
__global__ __launch_bounds__(256) void k_layer2(float* __restrict__ out,
                                                const float* __restrict__ b2, int N) {
    int w = (blockIdx.x * blockDim.x + threadIdx.x) >> 5;
    int lane = threadIdx.x & 31;
    if (w >= N) return;
    int beg = g_rowptr[w], end = g_rowptr[w + 1];
    float adv = g_ad2[w];
    int eslot = lane >> 4;
    int ch = lane & 15;

    float den = 0.0f, acc = 0.0f;
    for (int e = beg + eslot; e < end; e += 2) {
        int s = g_csr_src[e];
        float p = __expf(lrelu(g_as2[s] + adv));
        den += p;
        acc += p * g_h2[(size_t)s * NCLS + ch];
    }
    den += __shfl_xor_sync(0xFFFFFFFFu, den, 16);
    acc += __shfl_xor_sync(0xFFFFFFFFu, acc, 16);
    if (lane < 16) out[(size_t)w * NCLS + ch] = acc / den + b2[ch];
}

// ---------------- launch ---------------------------------------------------
extern "C" void kernel_launch(void* const* d_in, const int* in_sizes, int n_in,
                              void* d_out, int out_size) {
    const float* x    = (const float*)d_in[0];
    const int*   ei   = (const int*)d_in[1];
    const float* W1   = (const float*)d_in[2];
    const float* as1v = (const float*)d_in[3];
    const float* ad1v = (const float*)d_in[4];
    const float* b1   = (const float*)d_in[5];
    const float* W2   = (const float*)d_in[6];
    const float* as2v = (const float*)d_in[7];
    const float* ad2v = (const float*)d_in[8];
    const float* b2   = (const float*)d_in[9];
    float* out = (float*)d_out;

    int E = in_sizes[1] / 2;
    int N = in_sizes[0] / FIN;
    int tot = E + N;
    int n1 = N + 1;
    int nscan = (n1 + SCAN_BS - 1) / SCAN_BS;

    static cudaStream_t s1 = nullptr;
    static cudaEvent_t evRoot = nullptr, evB = nullptr;
    if (!s1) {
        cudaStreamCreate(&s1);
        cudaEventCreateWithFlags(&evRoot, cudaEventDisableTiming);
        cudaEventCreateWithFlags(&evB, cudaEventDisableTiming);
    }

    // fork: branch B (GEMM + fused attention projections) on s1
    cudaEventRecord(evRoot, 0);
    cudaStreamWaitEvent(s1, evRoot, 0);
    k_gemm1<<<(N + TBM - 1) / TBM, 256, 0, s1>>>(x, W1, as1v, ad1v, N);
    cudaEventRecord(evB, s1);

    // branch A (CSR build) on default stream
    k_init<<<(n1 + 255) / 256, 256>>>(ei, n1);
    k_hist<<<(tot + 255) / 256, 256>>>(ei, E, N);
    k_scan1<<<nscan, SCAN_BS>>>(n1);
    k_scan3<<<nscan, SCAN_BS>>>(n1);
    k_scatter<<<(tot + 255) / 256, 256>>>(ei, E, N);

    // join
    cudaStreamWaitEvent(0, evB, 0);
    k_layer1<<<(N * 32 + 255) / 256, 256>>>(N);
    k_fin1<<<(N + 255) / 256, 256>>>(b1, W2, as2v, ad2v, N);
    k_layer2<<<(N * 32 + 255) / 256, 256>>>(out, b2, N);
}

// round 16
// speedup vs baseline: 1.0374x; 1.0374x over previous
#include <cuda_runtime.h>
#include <cuda_fp16.h>
#include <cmath>
#include <cstdint>

#define NN     100000
#define EE     3200000
#define ETOT   (EE + NN)
#define FIN    512
#define H1D    64
#define HEADS  8
#define NCLS   16
#define SCAN_BS 512

// ---------------- scratch (device globals; no allocation) ----------------
__device__ __align__(16) static int    g_csr_src[ETOT];
__device__ static int    g_rowptr[NN + 1];
__device__ static int    g_cursor[NN];
__device__ static int    g_blocksum[512];
__device__ __align__(16) static __half g_h1h[(size_t)NN * H1D];   // fp16 h1
__device__ __align__(16) static float  g_as1[NN * HEADS];
__device__ __align__(16) static float  g_ad1[NN * HEADS];
__device__ __align__(16) static float  g_acc1[(size_t)NN * H1D];
__device__ __align__(16) static __half g_h2h[(size_t)NN * NCLS];  // fp16 h2
__device__ __align__(16) static float  g_as2[NN];
__device__ __align__(16) static float  g_ad2[NN];
__device__ static int g_is64;

__device__ __forceinline__ float lrelu(float v) { return v > 0.0f ? v : 0.2f * v; }
__device__ __forceinline__ uint32_t f2tf32(float f) {
    uint32_t r;
    asm("cvt.rna.tf32.f32 %0, %1;" : "=r"(r) : "f"(f));
    return r;
}

// ---------------- init: zero rowptr + detect edge dtype (block 0) ---------
__global__ void k_init(const int* __restrict__ ei, int n1) {
    int t = blockIdx.x * blockDim.x + threadIdx.x;
    if (t < n1) g_rowptr[t] = 0;
    if (blockIdx.x == 0) {
        __shared__ int s;
        if (threadIdx.x == 0) s = 1;
        __syncthreads();
        int bad = 0;
        for (int i = threadIdx.x; i < 1024; i += blockDim.x)
            if (ei[2 * i + 1] != 0) bad = 1;
        if (bad) atomicExch(&s, 0);
        __syncthreads();
        if (threadIdx.x == 0) g_is64 = s;
    }
}

// ---------------- histogram of dst (reads edge_index directly) -------------
__global__ void k_hist(const int* __restrict__ ei, int E, int N) {
    int t = blockIdx.x * blockDim.x + threadIdx.x;
    if (t >= E + N) return;
    int d;
    if (t < E) {
        d = g_is64 ? (int)((const long long*)ei)[(size_t)E + t]
                   : ei[(size_t)E + t];
    } else {
        d = t - E;
    }
    atomicAdd(&g_rowptr[d + 1], 1);
}

// ---------------- scan (rowptr): 2 kernels ---------------------------------
__global__ void k_scan1(int n) {
    __shared__ int sh[SCAN_BS];
    int i = blockIdx.x * SCAN_BS + threadIdx.x;
    int v = (i < n) ? g_rowptr[i] : 0;
    sh[threadIdx.x] = v;
    __syncthreads();
    for (int off = 1; off < SCAN_BS; off <<= 1) {
        int t = (threadIdx.x >= off) ? sh[threadIdx.x - off] : 0;
        __syncthreads();
        sh[threadIdx.x] += t;
        __syncthreads();
    }
    if (i < n) g_rowptr[i] = sh[threadIdx.x];
    if (threadIdx.x == SCAN_BS - 1) g_blocksum[blockIdx.x] = sh[threadIdx.x];
}
__global__ void k_scan3(int n) {
    __shared__ int off_s;
    int b = blockIdx.x;
    if (threadIdx.x < 32) {
        int sum = 0;
        for (int j = threadIdx.x; j < b; j += 32) sum += g_blocksum[j];
#pragma unroll
        for (int o = 16; o; o >>= 1) sum += __shfl_xor_sync(0xFFFFFFFFu, sum, o);
        if (threadIdx.x == 0) off_s = sum;
    }
    __syncthreads();
    int i = b * SCAN_BS + threadIdx.x;
    if (i < n) {
        int v = g_rowptr[i] + off_s;
        g_rowptr[i] = v;
        if (i < n - 1) g_cursor[i] = v;
    }
}

// ---------------- scatter (re-reads edge_index, decodes src+dst) -----------
__global__ void k_scatter(const int* __restrict__ ei, int E, int N) {
    int t = blockIdx.x * blockDim.x + threadIdx.x;
    if (t >= E + N) return;
    int s, d;
    if (t < E) {
        if (g_is64) {
            const long long* e64 = (const long long*)ei;
            s = (int)e64[t];
            d = (int)e64[(size_t)E + t];
        } else {
            s = ei[t];
            d = ei[(size_t)E + t];
        }
    } else {
        s = t - E;
        d = t - E;
    }
    int pos = atomicAdd(&g_cursor[d], 1);
    g_csr_src[pos] = s;
}

// ------- GEMM1 via tf32 mma.sync, fp16 h1 + fused attention epilogue -------
#define TBM 128
#define TBN 64
#define TBK 16
__global__ __launch_bounds__(256) void k_gemm1(const float* __restrict__ X,
                                               const float* __restrict__ W,
                                               const float* __restrict__ att_s,
                                               const float* __restrict__ att_d, int M) {
    __shared__ float xs[TBK][TBM + 4];
    __shared__ float ws[TBK][TBN + 4];
    const int tid = threadIdx.x;
    const int wid = tid >> 5, lane = tid & 31;
    const int wm = wid >> 1, wn = wid & 1;
    const int grp = lane >> 2, tcol = lane & 3;
    const int row0 = blockIdx.x * TBM;

    float c[2][4][4];
#pragma unroll
    for (int mt = 0; mt < 2; mt++)
#pragma unroll
        for (int nt = 0; nt < 4; nt++)
#pragma unroll
            for (int q = 0; q < 4; q++) c[mt][nt][q] = 0.0f;

    for (int k0 = 0; k0 < FIN; k0 += TBK) {
#pragma unroll
        for (int i = 0; i < 2; i++) {
            int s = tid + i * 256;
            int r = s >> 2;
            int c4 = s & 3;
            float4 v = make_float4(0.f, 0.f, 0.f, 0.f);
            int gr = row0 + r;
            if (gr < M)
                v = *(const float4*)(X + (size_t)gr * FIN + k0 + c4 * 4);
            xs[c4 * 4 + 0][r] = __uint_as_float(f2tf32(v.x));
            xs[c4 * 4 + 1][r] = __uint_as_float(f2tf32(v.y));
            xs[c4 * 4 + 2][r] = __uint_as_float(f2tf32(v.z));
            xs[c4 * 4 + 3][r] = __uint_as_float(f2tf32(v.w));
        }
        {
            int r = tid >> 4;
            int c4 = tid & 15;
            float4 v = *(const float4*)(W + (size_t)(k0 + r) * TBN + c4 * 4);
            ws[r][c4 * 4 + 0] = __uint_as_float(f2tf32(v.x));
            ws[r][c4 * 4 + 1] = __uint_as_float(f2tf32(v.y));
            ws[r][c4 * 4 + 2] = __uint_as_float(f2tf32(v.z));
            ws[r][c4 * 4 + 3] = __uint_as_float(f2tf32(v.w));
        }
        __syncthreads();
#pragma unroll
        for (int kc = 0; kc < 2; kc++) {
            const int kb = kc * 8;
            uint32_t a[2][4];
#pragma unroll
            for (int mt = 0; mt < 2; mt++) {
                int m0 = wm * 32 + mt * 16;
                a[mt][0] = __float_as_uint(xs[kb + tcol][m0 + grp]);
                a[mt][1] = __float_as_uint(xs[kb + tcol][m0 + grp + 8]);
                a[mt][2] = __float_as_uint(xs[kb + tcol + 4][m0 + grp]);
                a[mt][3] = __float_as_uint(xs[kb + tcol + 4][m0 + grp + 8]);
            }
            uint32_t b[4][2];
#pragma unroll
            for (int nt = 0; nt < 4; nt++) {
                int n0 = wn * 32 + nt * 8;
                b[nt][0] = __float_as_uint(ws[kb + tcol][n0 + grp]);
                b[nt][1] = __float_as_uint(ws[kb + tcol + 4][n0 + grp]);
            }
#pragma unroll
            for (int mt = 0; mt < 2; mt++)
#pragma unroll
                for (int nt = 0; nt < 4; nt++) {
                    asm volatile(
                        "mma.sync.aligned.m16n8k8.row.col.f32.tf32.tf32.f32 "
                        "{%0,%1,%2,%3}, {%4,%5,%6,%7}, {%8,%9}, {%0,%1,%2,%3};"
                        : "+f"(c[mt][nt][0]), "+f"(c[mt][nt][1]),
                          "+f"(c[mt][nt][2]), "+f"(c[mt][nt][3])
                        : "r"(a[mt][0]), "r"(a[mt][1]), "r"(a[mt][2]), "r"(a[mt][3]),
                          "r"(b[nt][0]), "r"(b[nt][1]));
                }
        }
        __syncthreads();
    }
    // epilogue: fp16 h1 store + fused attention projections.
#pragma unroll
    for (int mt = 0; mt < 2; mt++) {
#pragma unroll
        for (int nt = 0; nt < 4; nt++) {
            int head = wn * 4 + nt;
            int row = row0 + wm * 32 + mt * 16 + grp;
            int col = wn * 32 + nt * 8 + tcol * 2;
            if (row < M)
                *(__half2*)&g_h1h[(size_t)row * H1D + col] =
                    __floats2half2_rn(c[mt][nt][0], c[mt][nt][1]);
            if (row + 8 < M)
                *(__half2*)&g_h1h[(size_t)(row + 8) * H1D + col] =
                    __floats2half2_rn(c[mt][nt][2], c[mt][nt][3]);
            float s0 = __ldg(att_s + head * 8 + tcol * 2);
            float s1 = __ldg(att_s + head * 8 + tcol * 2 + 1);
            float d0 = __ldg(att_d + head * 8 + tcol * 2);
            float d1 = __ldg(att_d + head * 8 + tcol * 2 + 1);
            float asA = c[mt][nt][0] * s0 + c[mt][nt][1] * s1;
            float adA = c[mt][nt][0] * d0 + c[mt][nt][1] * d1;
            float asB = c[mt][nt][2] * s0 + c[mt][nt][3] * s1;
            float adB = c[mt][nt][2] * d0 + c[mt][nt][3] * d1;
            asA += __shfl_xor_sync(0xFFFFFFFFu, asA, 1);
            asA += __shfl_xor_sync(0xFFFFFFFFu, asA, 2);
            adA += __shfl_xor_sync(0xFFFFFFFFu, adA, 1);
            adA += __shfl_xor_sync(0xFFFFFFFFu, adA, 2);
            asB += __shfl_xor_sync(0xFFFFFFFFu, asB, 1);
            asB += __shfl_xor_sync(0xFFFFFFFFu, asB, 2);
            adB += __shfl_xor_sync(0xFFFFFFFFu, adB, 1);
            adB += __shfl_xor_sync(0xFFFFFFFFu, adB, 2);
            if (tcol == 0) {
                if (row < M) {
                    g_as1[row * 8 + head] = asA;
                    g_ad1[row * 8 + head] = adA;
                }
                if (row + 8 < M) {
                    g_as1[(row + 8) * 8 + head] = asB;
                    g_ad1[(row + 8) * 8 + head] = adB;
                }
            }
        }
    }
}

// ---------------- fused layer1, single pass, fp16 gathers -----------------
__global__ __launch_bounds__(256) void k_layer1(int N) {
    int w = (blockIdx.x * blockDim.x + threadIdx.x) >> 5;
    int lane = threadIdx.x & 31;
    if (w >= N) return;
    int beg = g_rowptr[w], end = g_rowptr[w + 1];
    int head = lane & 7;
    int eslot = lane >> 3;
    float adsel = g_ad1[w * 8 + head];

    float den = 0.0f;
    float acc[8];
#pragma unroll
    for (int j = 0; j < 8; j++) acc[j] = 0.0f;
    for (int e = beg + eslot; e < end; e += 4) {
        int s = g_csr_src[e];
        float p = __expf(lrelu(g_as1[s * 8 + head] + adsel));
        den += p;
        uint4 raw = *(const uint4*)&g_h1h[(size_t)s * H1D + head * 8];
        float2 q0 = __half22float2(*(__half2*)&raw.x);
        float2 q1 = __half22float2(*(__half2*)&raw.y);
        float2 q2 = __half22float2(*(__half2*)&raw.z);
        float2 q3 = __half22float2(*(__half2*)&raw.w);
        acc[0] += p * q0.x; acc[1] += p * q0.y;
        acc[2] += p * q1.x; acc[3] += p * q1.y;
        acc[4] += p * q2.x; acc[5] += p * q2.y;
        acc[6] += p * q3.x; acc[7] += p * q3.y;
    }
    den += __shfl_xor_sync(0xFFFFFFFFu, den, 8);
    den += __shfl_xor_sync(0xFFFFFFFFu, den, 16);
#pragma unroll
    for (int j = 0; j < 8; j++) {
        acc[j] += __shfl_xor_sync(0xFFFFFFFFu, acc[j], 8);
        acc[j] += __shfl_xor_sync(0xFFFFFFFFu, acc[j], 16);
    }
    if (eslot == 0) {
        float rden = 1.0f / den;
        *(float4*)&g_acc1[(size_t)w * H1D + head * 8] =
            make_float4(acc[0] * rden, acc[1] * rden, acc[2] * rden, acc[3] * rden);
        *(float4*)&g_acc1[(size_t)w * H1D + head * 8 + 4] =
            make_float4(acc[4] * rden, acc[5] * rden, acc[6] * rden, acc[7] * rden);
    }
}

// ---------------- finalize1: +b1, elu, @W2, attention dots; fp16 h2 -------
__global__ __launch_bounds__(256) void k_fin1(const float* __restrict__ b1,
                                              const float* __restrict__ W2,
                                              const float* __restrict__ as2v,
                                              const float* __restrict__ ad2v, int N) {
    __shared__ float w2s[H1D * NCLS];
    __shared__ float b1s[H1D];
    __shared__ float s2[NCLS], d2[NCLS];
    int tid = threadIdx.x;
    for (int i = tid; i < H1D * NCLS; i += blockDim.x) w2s[i] = W2[i];
    if (tid < H1D) b1s[tid] = b1[tid];
    if (tid < NCLS) { s2[tid] = as2v[tid]; d2[tid] = ad2v[tid]; }
    __syncthreads();
    int n = blockIdx.x * blockDim.x + tid;
    if (n >= N) return;

    float h[H1D];
    const float4* ap = (const float4*)g_acc1 + (size_t)n * 16;
#pragma unroll
    for (int q = 0; q < 16; q++) {
        float4 v = ap[q];
        h[q * 4 + 0] = v.x; h[q * 4 + 1] = v.y; h[q * 4 + 2] = v.z; h[q * 4 + 3] = v.w;
    }
#pragma unroll
    for (int c = 0; c < H1D; c++) {
        float v = h[c] + b1s[c];
        h[c] = v > 0.0f ? v : expm1f(v);
    }
    float o[NCLS];
#pragma unroll
    for (int j = 0; j < NCLS; j++) o[j] = 0.0f;
#pragma unroll
    for (int c = 0; c < H1D; c++) {
        float hv = h[c];
#pragma unroll
        for (int j = 0; j < NCLS; j++) o[j] += hv * w2s[c * NCLS + j];
    }
    __half2* h2p = (__half2*)&g_h2h[(size_t)n * NCLS];
#pragma unroll
    for (int q = 0; q < 8; q++)
        h2p[q] = __floats2half2_rn(o[q * 2], o[q * 2 + 1]);
    float as = 0.0f, ad = 0.0f;
#pragma unroll
    for (int j = 0; j < NCLS; j++) { as += o[j] * s2[j]; ad += o[j] * d2[j]; }
    g_as2[n] = as;
    g_ad2[n] = ad;
}

// ---------------- fused layer2, single pass, fp16 gathers, 4 slots --------
__global__ __launch_bounds__(256) void k_layer2(float* __restrict__ out,
                                                const float* __restrict__ b2, int N) {
    int w = (blockIdx.x * blockDim.x + threadIdx.x) >> 5;
    int lane = threadIdx.x & 31;
    if (w >= N) return;
    int beg = g_rowptr[w], end = g_rowptr[w + 1];
    float adv = g_ad2[w];
    int eslot = lane >> 3;      // 4 edge slots
    int cp = lane & 7;          // 8 channel pairs

    float den = 0.0f, a0 = 0.0f, a1 = 0.0f;
    for (int e = beg + eslot; e < end; e += 4) {
        int s = g_csr_src[e];
        float p = __expf(lrelu(g_as2[s] + adv));
        den += p;
        float2 f = __half22float2(*(const __half2*)&g_h2h[(size_t)s * NCLS + cp * 2]);
        a0 += p * f.x;
        a1 += p * f.y;
    }
    den += __shfl_xor_sync(0xFFFFFFFFu, den, 8);
    den += __shfl_xor_sync(0xFFFFFFFFu, den, 16);
    a0 += __shfl_xor_sync(0xFFFFFFFFu, a0, 8);
    a0 += __shfl_xor_sync(0xFFFFFFFFu, a0, 16);
    a1 += __shfl_xor_sync(0xFFFFFFFFu, a1, 8);
    a1 += __shfl_xor_sync(0xFFFFFFFFu, a1, 16);
    if (eslot == 0) {
        float rden = 1.0f / den;
        *(float2*)&out[(size_t)w * NCLS + cp * 2] =
            make_float2(a0 * rden + b2[cp * 2], a1 * rden + b2[cp * 2 + 1]);
    }
}

// ---------------- launch ---------------------------------------------------
extern "C" void kernel_launch(void* const* d_in, const int* in_sizes, int n_in,
                              void* d_out, int out_size) {
    const float* x    = (const float*)d_in[0];
    const int*   ei   = (const int*)d_in[1];
    const float* W1   = (const float*)d_in[2];
    const float* as1v = (const float*)d_in[3];
    const float* ad1v = (const float*)d_in[4];
    const float* b1   = (const float*)d_in[5];
    const float* W2   = (const float*)d_in[6];
    const float* as2v = (const float*)d_in[7];
    const float* ad2v = (const float*)d_in[8];
    const float* b2   = (const float*)d_in[9];
    float* out = (float*)d_out;

    int E = in_sizes[1] / 2;
    int N = in_sizes[0] / FIN;
    int tot = E + N;
    int n1 = N + 1;
    int nscan = (n1 + SCAN_BS - 1) / SCAN_BS;

    static cudaStream_t s1 = nullptr;
    static cudaEvent_t evRoot = nullptr, evB = nullptr;
    if (!s1) {
        cudaStreamCreate(&s1);
        cudaEventCreateWithFlags(&evRoot, cudaEventDisableTiming);
        cudaEventCreateWithFlags(&evB, cudaEventDisableTiming);
    }

    // fork: branch B (GEMM + fused attention projections) on s1
    cudaEventRecord(evRoot, 0);
    cudaStreamWaitEvent(s1, evRoot, 0);
    k_gemm1<<<(N + TBM - 1) / TBM, 256, 0, s1>>>(x, W1, as1v, ad1v, N);
    cudaEventRecord(evB, s1);

    // branch A (CSR build) on default stream
    k_init<<<(n1 + 255) / 256, 256>>>(ei, n1);
    k_hist<<<(tot + 255) / 256, 256>>>(ei, E, N);
    k_scan1<<<nscan, SCAN_BS>>>(n1);
    k_scan3<<<nscan, SCAN_BS>>>(n1);
    k_scatter<<<(tot + 255) / 256, 256>>>(ei, E, N);

    // join
    cudaStreamWaitEvent(0, evB, 0);
    k_layer1<<<(N * 32 + 255) / 256, 256>>>(N);
    k_fin1<<<(N + 255) / 256, 256>>>(b1, W2, as2v, ad2v, N);
    k_layer2<<<(N * 32 + 255) / 256, 256>>>(out, b2, N);
}